// round 4
// baseline (speedup 1.0000x reference)
#include <cuda_runtime.h>
#include <math.h>

// ---------------------------------------------------------------------------
// Problem constants (AttentionalLaneLSTM): M=4096, N=256, EMB=64, H=128,
// ENC=128, T=100. Gates G = 4*H = 512. K total = H + EMB = 192.
// ---------------------------------------------------------------------------
#define M_MAX   4096
#define T_STEPS 100
#define EMBD    64
#define HID     128
#define GDIM    512
#define KTOT    192
#define NOBS    256
#define ENCD    128
#define ROWS    16      // batch rows per LSTM CTA
#define PAIRS   8       // ROWS/2 (f32x2-packed row pairs)

// Scratch (device globals — no dynamic allocation allowed)
__device__ float g_scores[NOBS * T_STEPS];                 // softmax attention scores
__device__ __align__(16) float g_Wpack[2 * KTOT * GDIM];   // [dir][k][u*4+gate]
__device__ float g_pre[M_MAX * 1024];                      // concat features per row

// ---------------------------------------------------------------------------
// f32x2 helpers (FFMA2 — only reachable via PTX fma.rn.f32x2 on sm_103a)
// ---------------------------------------------------------------------------
__device__ __forceinline__ unsigned long long pack2(float a, float b) {
    unsigned long long r;
    asm("mov.b64 %0, {%1,%2};" : "=l"(r) : "f"(a), "f"(b));
    return r;
}
__device__ __forceinline__ float2 unpack2(unsigned long long v) {
    float2 r;
    asm("mov.b64 {%0,%1}, %2;" : "=f"(r.x), "=f"(r.y) : "l"(v));
    return r;
}
__device__ __forceinline__ void fma2(unsigned long long& acc,
                                     unsigned long long a, unsigned long long b) {
    asm("fma.rn.f32x2 %0, %1, %2, %0;" : "+l"(acc) : "l"(a), "l"(b));
}

// Fast-but-accurate activations (EX2-based; rel err ~1e-6, far under 1e-3 budget)
__device__ __forceinline__ float sigf(float x) {
    return __fdividef(1.0f, 1.0f + __expf(-x));
}
__device__ __forceinline__ float tanhfast(float x) {
    return __fdividef(2.0f, 1.0f + __expf(-2.0f * x)) - 1.0f;
}

// ---------------------------------------------------------------------------
// Kernel 1: repack LSTM weights into [dir][k][u*4 + gate] so the recurrence
// inner loop does one LDG.128 per k covering all 4 gates of unit u.
//   k < 128  -> Whh[k][gate*128+u] ; k >= 128 -> Wih[k-128][gate*128+u]
// ---------------------------------------------------------------------------
__global__ void pack_kernel(const float* __restrict__ Wih_f,
                            const float* __restrict__ Whh_f,
                            const float* __restrict__ Wih_b,
                            const float* __restrict__ Whh_b) {
    int idx = blockIdx.x * blockDim.x + threadIdx.x;
    if (idx >= 2 * KTOT * GDIM) return;
    int d   = idx / (KTOT * GDIM);
    int rem = idx % (KTOT * GDIM);
    int k   = rem / GDIM;
    int q   = rem % GDIM;
    int u   = q >> 2;
    int g   = q & 3;
    int col = g * HID + u;
    const float* Whh = d ? Whh_b : Whh_f;
    const float* Wih = d ? Wih_b : Wih_f;
    g_Wpack[idx] = (k < HID) ? Whh[k * GDIM + col] : Wih[(k - HID) * GDIM + col];
}

// ---------------------------------------------------------------------------
// Kernel 2: attention scores = softmax(relu(obs @ attn_W + attn_b), axis=1)
// One block per obs row (256 blocks, 128 threads).
// ---------------------------------------------------------------------------
__global__ void attn_kernel(const float* __restrict__ obs,
                            const float* __restrict__ W,
                            const float* __restrict__ b) {
    int n = blockIdx.x;
    int tid = threadIdx.x;
    __shared__ float obs_s[128];
    __shared__ float red[128];

    obs_s[tid] = obs[n * 128 + tid];
    __syncthreads();

    float a = -1e30f;
    if (tid < T_STEPS) {
        a = b[tid];
#pragma unroll 8
        for (int k = 0; k < 128; k++) a = fmaf(obs_s[k], W[k * T_STEPS + tid], a);
        a = fmaxf(a, 0.0f);
    }
    // max reduce
    red[tid] = a;
    __syncthreads();
    for (int s = 64; s > 0; s >>= 1) {
        if (tid < s) red[tid] = fmaxf(red[tid], red[tid + s]);
        __syncthreads();
    }
    float m = red[0];
    __syncthreads();
    float e = 0.0f;
    if (tid < T_STEPS) e = expf(a - m);
    red[tid] = e;
    __syncthreads();
    for (int s = 64; s > 0; s >>= 1) {
        if (tid < s) red[tid] += red[tid + s];
        __syncthreads();
    }
    float ssum = red[0];
    if (tid < T_STEPS) g_scores[n * T_STEPS + tid] = e / ssum;
}

// ---------------------------------------------------------------------------
// Kernel 3: fused bidirectional LSTM + embed-on-the-fly + online reductions.
// Grid: 2 directions x (M/ROWS) blocks of 128 threads.
// Thread u owns hidden unit u: gate columns {u, 128+u, 256+u, 384+u}.
// 16 rows handled as 8 f32x2-packed pairs.
// Per step: publish h -> smem; stage x_t = relu(feat4 @ embed_W); then
// g = [h|x] @ Wpack via FFMA2; then per-thread gate math + online
// front/back/max/attn reductions into g_pre.
// ---------------------------------------------------------------------------
__global__ void __launch_bounds__(128)
lstm_kernel(const float* __restrict__ lf,
            const float* __restrict__ embW, const float* __restrict__ embB,
            const float* __restrict__ b_f,  const float* __restrict__ b_b,
            const float* __restrict__ h0,   const float* __restrict__ c0,
            const int*   __restrict__ mask, int Mrows) {
    int nblk = Mrows / ROWS;
    int dir  = blockIdx.x / nblk;
    int mblk = blockIdx.x % nblk;
    int r0   = mblk * ROWS;
    int u    = threadIdx.x;

    __shared__ float2 h2s[PAIRS][HID];   // h pairs: h2s[p][k] = (h[2p][k], h[2p+1][k])
    __shared__ float2 x2s[PAIRS][EMBD];  // x pairs for current step
    __shared__ float  attv[ROWS];
    __shared__ int    mrow[ROWS];
    __shared__ float  eW[4 * EMBD];
    __shared__ float  eB[EMBD];

    if (u < ROWS) mrow[u] = mask[r0 + u];
    eW[u]       = embW[u];
    eW[u + 128] = embW[u + 128];
    if (u < EMBD) eB[u] = embB[u];

    const float* bias = dir ? b_b : b_f;
    const float4* Wp = (const float4*)(g_Wpack + dir * KTOT * GDIM) + u;

    float bg0 = bias[u], bg1 = bias[128 + u], bg2 = bias[256 + u], bg3 = bias[384 + u];
    float h0v = h0[dir * HID + u];
    float c0v = c0[dir * HID + u];

    float2 hreg[PAIRS], c2[PAIRS], hmax[PAIRS], hatt[PAIRS];
#pragma unroll
    for (int p = 0; p < PAIRS; p++) {
        hreg[p] = make_float2(h0v, h0v);
        c2[p]   = make_float2(c0v, c0v);
        hmax[p] = make_float2(-1e30f, -1e30f);
        hatt[p] = make_float2(0.0f, 0.0f);
    }

    for (int s = 0; s < T_STEPS; s++) {
        int t = dir ? (T_STEPS - 1 - s) : s;

        __syncthreads();  // S1: all threads finished previous k-loop reads

        // publish h (unit u, all row pairs)
#pragma unroll
        for (int p = 0; p < PAIRS; p++) h2s[p][u] = hreg[p];

        // stage x_t: lane_embed[r][t][e] = relu(feat4 . embW[:,e] + embB[e])
        // feat[r][k] = lf[(r0+r)*600 + 200 + t*4 + k]
#pragma unroll
        for (int i = 0; i < 8; i++) {
            int idx = u + i * 128;           // 0..1023 over (r,e)
            int r = idx >> 6, e = idx & 63;
            const float* fb = lf + (r0 + r) * 600 + 200 + t * 4;
            float f0 = fb[0], f1 = fb[1], f2 = fb[2], f3 = fb[3];
            float v = eB[e];
            v = fmaf(f0, eW[e],        v);
            v = fmaf(f1, eW[64  + e],  v);
            v = fmaf(f2, eW[128 + e],  v);
            v = fmaf(f3, eW[192 + e],  v);
            v = fmaxf(v, 0.0f);
            ((float*)&x2s[r >> 1][e])[r & 1] = v;
        }
        if (u < ROWS) attv[u] = g_scores[mrow[u] * T_STEPS + t];

        __syncthreads();  // S2: h/x staged, begin GEMV

        unsigned long long a0[PAIRS], a1[PAIRS], a2[PAIRS], a3[PAIRS];
#pragma unroll
        for (int p = 0; p < PAIRS; p++) {
            a0[p] = pack2(bg0, bg0); a1[p] = pack2(bg1, bg1);
            a2[p] = pack2(bg2, bg2); a3[p] = pack2(bg3, bg3);
        }

        // h part: k = 0..127
#pragma unroll 4
        for (int k = 0; k < HID; k++) {
            float4 w4 = Wp[k * 128];
            unsigned long long w0 = pack2(w4.x, w4.x);
            unsigned long long w1 = pack2(w4.y, w4.y);
            unsigned long long w2 = pack2(w4.z, w4.z);
            unsigned long long w3 = pack2(w4.w, w4.w);
#pragma unroll
            for (int p = 0; p < PAIRS; p++) {
                unsigned long long hv = *(const unsigned long long*)&h2s[p][k];
                fma2(a0[p], hv, w0); fma2(a1[p], hv, w1);
                fma2(a2[p], hv, w2); fma2(a3[p], hv, w3);
            }
        }
        // x part: k = 128..191
#pragma unroll 4
        for (int k = 0; k < EMBD; k++) {
            float4 w4 = Wp[(HID + k) * 128];
            unsigned long long w0 = pack2(w4.x, w4.x);
            unsigned long long w1 = pack2(w4.y, w4.y);
            unsigned long long w2 = pack2(w4.z, w4.z);
            unsigned long long w3 = pack2(w4.w, w4.w);
#pragma unroll
            for (int p = 0; p < PAIRS; p++) {
                unsigned long long xv = *(const unsigned long long*)&x2s[p][k];
                fma2(a0[p], xv, w0); fma2(a1[p], xv, w1);
                fma2(a2[p], xv, w2); fma2(a3[p], xv, w3);
            }
        }

        // gate math + online reductions (all thread-local for unit u)
#pragma unroll
        for (int p = 0; p < PAIRS; p++) {
            float2 gi = unpack2(a0[p]);
            float2 gf = unpack2(a1[p]);
            float2 gg = unpack2(a2[p]);
            float2 go = unpack2(a3[p]);
            float cx = sigf(gf.x) * c2[p].x + sigf(gi.x) * tanhfast(gg.x);
            float cy = sigf(gf.y) * c2[p].y + sigf(gi.y) * tanhfast(gg.y);
            c2[p].x = cx; c2[p].y = cy;
            float hx = sigf(go.x) * tanhfast(cx);
            float hy = sigf(go.y) * tanhfast(cy);
            hreg[p] = make_float2(hx, hy);
            hmax[p].x = fmaxf(hmax[p].x, hx);
            hmax[p].y = fmaxf(hmax[p].y, hy);
            float ax = attv[2 * p], ay = attv[2 * p + 1];
            hatt[p].x = fmaf(hx, ax, hatt[p].x);
            hatt[p].y = fmaf(hy, ay, hatt[p].y);
            if (t == 0) {  // front section: cols [dir*128, dir*128+128)
                g_pre[(r0 + 2 * p)     * 1024 + dir * HID + u] = hx;
                g_pre[(r0 + 2 * p + 1) * 1024 + dir * HID + u] = hy;
            }
            if (t == T_STEPS - 1) {  // back section: cols [256 + dir*128, ...)
                g_pre[(r0 + 2 * p)     * 1024 + 256 + dir * HID + u] = hx;
                g_pre[(r0 + 2 * p + 1) * 1024 + 256 + dir * HID + u] = hy;
            }
        }
    }

    // max section (512 + dir*128) and attention section (768 + dir*128)
#pragma unroll
    for (int p = 0; p < PAIRS; p++) {
        g_pre[(r0 + 2 * p)     * 1024 + 512 + dir * HID + u] = hmax[p].x;
        g_pre[(r0 + 2 * p + 1) * 1024 + 512 + dir * HID + u] = hmax[p].y;
        g_pre[(r0 + 2 * p)     * 1024 + 768 + dir * HID + u] = hatt[p].x;
        g_pre[(r0 + 2 * p + 1) * 1024 + 768 + dir * HID + u] = hatt[p].y;
    }
}

// ---------------------------------------------------------------------------
// Kernel 4: out = relu(pre(M,1024) @ enc_W(1024,128) + enc_b)
// 16 rows per block (8 f32x2 pairs), 128 threads = one output column each.
// ---------------------------------------------------------------------------
__global__ void __launch_bounds__(128)
out_kernel(const float* __restrict__ encW, const float* __restrict__ encB,
           float* __restrict__ out) {
    const int R2 = 16;
    int r0 = blockIdx.x * R2;
    int c  = threadIdx.x;
    __shared__ float2 ps[R2 / 2][64];

    float bc = encB[c];
    unsigned long long acc[R2 / 2];
#pragma unroll
    for (int p = 0; p < R2 / 2; p++) acc[p] = pack2(bc, bc);

    for (int kt = 0; kt < 1024; kt += 64) {
        __syncthreads();
#pragma unroll
        for (int i = 0; i < 8; i++) {
            int idx = c + i * 128;          // 0..1023 over (r, kk)
            int r = idx >> 6, kk = idx & 63;
            ((float*)&ps[r >> 1][kk])[r & 1] = g_pre[(r0 + r) * 1024 + kt + kk];
        }
        __syncthreads();
#pragma unroll 4
        for (int kk = 0; kk < 64; kk++) {
            float w = encW[(kt + kk) * 128 + c];
            unsigned long long w2 = pack2(w, w);
#pragma unroll
            for (int p = 0; p < R2 / 2; p++) {
                unsigned long long pv = *(const unsigned long long*)&ps[p][kk];
                fma2(acc[p], pv, w2);
            }
        }
    }
#pragma unroll
    for (int p = 0; p < R2 / 2; p++) {
        float2 v = unpack2(acc[p]);
        out[(r0 + 2 * p)     * 128 + c] = fmaxf(v.x, 0.0f);
        out[(r0 + 2 * p + 1) * 128 + c] = fmaxf(v.y, 0.0f);
    }
}

// ---------------------------------------------------------------------------
// Launch
// ---------------------------------------------------------------------------
extern "C" void kernel_launch(void* const* d_in, const int* in_sizes, int n_in,
                              void* d_out, int out_size) {
    const float* lf    = (const float*)d_in[0];   // lane_features (M,600)
    const float* obs   = (const float*)d_in[1];   // obs_encoding (N,128)
    const float* embW  = (const float*)d_in[2];   // (4,64)
    const float* embB  = (const float*)d_in[3];   // (64)
    const float* attW  = (const float*)d_in[4];   // (128,100)
    const float* attB  = (const float*)d_in[5];   // (100)
    const float* Wih_f = (const float*)d_in[6];   // (64,512)
    const float* Whh_f = (const float*)d_in[7];   // (128,512)
    const float* b_f   = (const float*)d_in[8];   // (512)
    const float* Wih_b = (const float*)d_in[9];
    const float* Whh_b = (const float*)d_in[10];
    const float* b_b   = (const float*)d_in[11];
    const float* h0    = (const float*)d_in[12];  // (2,1,128)
    const float* c0    = (const float*)d_in[13];
    const float* encW  = (const float*)d_in[14];  // (1024,128)
    const float* encB  = (const float*)d_in[15];  // (128)
    const int*   mask  = (const int*)d_in[16];    // (M,1)

    int M    = in_sizes[16];       // 4096
    int Nobs = in_sizes[1] / 128;  // 256

    pack_kernel<<<(2 * KTOT * GDIM + 255) / 256, 256>>>(Wih_f, Whh_f, Wih_b, Whh_b);
    attn_kernel<<<Nobs, 128>>>(obs, attW, attB);
    lstm_kernel<<<2 * (M / ROWS), 128>>>(lf, embW, embB, b_f, b_b, h0, c0, mask, M);
    out_kernel<<<M / 16, 128>>>(encW, encB, (float*)d_out);
}

// round 6
// speedup vs baseline: 1.2463x; 1.2463x over previous
#include <cuda_runtime.h>
#include <math.h>

// ---------------------------------------------------------------------------
// AttentionalLaneLSTM: M=4096, N=256, EMB=64, H=128, ENC=128, T=100.
// ---------------------------------------------------------------------------
#define M_MAX   4096
#define T_STEPS 100
#define EMBD    64
#define HID     128
#define GDIM    512
#define NOBS    256
#define ROWS    8       // batch rows per recurrent CTA
#define PAIRS   4       // ROWS/2 f32x2-packed row pairs

// Scratch (device globals — no dynamic allocation allowed)
__device__ float g_scores[NOBS * T_STEPS];                  // softmax attn
__device__ __align__(16) float g_Whp[2 * HID  * GDIM];      // [dir][k][u*4+g]
__device__ __align__(16) float g_Wip[2 * EMBD * GDIM];      // [dir][k][u*4+g]
__device__ __align__(16) float g_xg[2 * T_STEPS * (M_MAX / ROWS) * PAIRS * HID * 8];
__device__ float g_pre[M_MAX * 1024];                       // concat features

// ---------------------------------------------------------------------------
// f32x2 helpers (FFMA2 — only reachable via PTX fma.rn.f32x2 on sm_103a)
// ---------------------------------------------------------------------------
__device__ __forceinline__ unsigned long long pack2(float a, float b) {
    unsigned long long r;
    asm("mov.b64 %0, {%1,%2};" : "=l"(r) : "f"(a), "f"(b));
    return r;
}
__device__ __forceinline__ float2 unpack2(unsigned long long v) {
    float2 r;
    asm("mov.b64 {%0,%1}, %2;" : "=f"(r.x), "=f"(r.y) : "l"(v));
    return r;
}
__device__ __forceinline__ void fma2(unsigned long long& acc,
                                     unsigned long long a, unsigned long long b) {
    asm("fma.rn.f32x2 %0, %1, %2, %0;" : "+l"(acc) : "l"(a), "l"(b));
}

__device__ __forceinline__ float sigf(float x) {
    return __fdividef(1.0f, 1.0f + __expf(-x));
}
__device__ __forceinline__ float tanhfast(float x) {
    return __fdividef(2.0f, 1.0f + __expf(-2.0f * x)) - 1.0f;
}

// ---------------------------------------------------------------------------
// Kernel 1: repack weights into [dir][k][u*4 + gate] (gate-interleaved per unit)
// ---------------------------------------------------------------------------
__global__ void pack_kernel(const float* __restrict__ Wih_f,
                            const float* __restrict__ Whh_f,
                            const float* __restrict__ Wih_b,
                            const float* __restrict__ Whh_b) {
    int idx = blockIdx.x * blockDim.x + threadIdx.x;
    if (idx >= 2 * 192 * GDIM) return;
    int d   = idx / (192 * GDIM);
    int rem = idx % (192 * GDIM);
    int k   = rem / GDIM;
    int q   = rem % GDIM;
    int u   = q >> 2;
    int g   = q & 3;
    int col = g * HID + u;
    if (k < HID) {
        const float* Whh = d ? Whh_b : Whh_f;
        g_Whp[(d * HID + k) * GDIM + q] = Whh[k * GDIM + col];
    } else {
        const float* Wih = d ? Wih_b : Wih_f;
        g_Wip[(d * EMBD + (k - HID)) * GDIM + q] = Wih[(k - HID) * GDIM + col];
    }
}

// ---------------------------------------------------------------------------
// Kernel 2: attention scores = softmax(relu(obs @ attn_W + attn_b), axis=1)
// ---------------------------------------------------------------------------
__global__ void attn_kernel(const float* __restrict__ obs,
                            const float* __restrict__ W,
                            const float* __restrict__ b) {
    int n = blockIdx.x;
    int tid = threadIdx.x;
    __shared__ float obs_s[128];
    __shared__ float red[128];

    obs_s[tid] = obs[n * 128 + tid];
    __syncthreads();

    float a = -1e30f;
    if (tid < T_STEPS) {
        a = b[tid];
#pragma unroll 8
        for (int k = 0; k < 128; k++) a = fmaf(obs_s[k], W[k * T_STEPS + tid], a);
        a = fmaxf(a, 0.0f);
    }
    red[tid] = a;
    __syncthreads();
    for (int s = 64; s > 0; s >>= 1) {
        if (tid < s) red[tid] = fmaxf(red[tid], red[tid + s]);
        __syncthreads();
    }
    float m = red[0];
    __syncthreads();
    float e = 0.0f;
    if (tid < T_STEPS) e = expf(a - m);
    red[tid] = e;
    __syncthreads();
    for (int s = 64; s > 0; s >>= 1) {
        if (tid < s) red[tid] += red[tid + s];
        __syncthreads();
    }
    float ssum = red[0];
    if (tid < T_STEPS) g_scores[n * T_STEPS + tid] = e / ssum;
}

// ---------------------------------------------------------------------------
// Kernel 3: precompute x-gates for ALL (dir,t,m):
//   xg = relu(feat4 @ embW + embB) @ Wih + b   (bias folded here)
// No recurrence -> sync-light, runs near fma-pipe peak.
// Grid: 2 * (M/ROWS) CTAs, 128 threads. Output tile per (dir,t,mblk):
//   [pair(4)][u(128)][gate(4)] as float2 (row pair) = 4096 floats.
// ---------------------------------------------------------------------------
__global__ void __launch_bounds__(128)
xgate_kernel(const float* __restrict__ lf,
             const float* __restrict__ embW, const float* __restrict__ embB,
             const float* __restrict__ b_f,  const float* __restrict__ b_b,
             int Mrows) {
    int nblk = Mrows / ROWS;
    int dir  = blockIdx.x / nblk;
    int mblk = blockIdx.x % nblk;
    int r0   = mblk * ROWS;
    int u    = threadIdx.x;

    __shared__ float2 x2s[PAIRS][EMBD];
    __shared__ float  eW[4 * EMBD];
    __shared__ float  eB[EMBD];

    eW[u]       = embW[u];
    eW[u + 128] = embW[u + 128];
    if (u < EMBD) eB[u] = embB[u];

    const float* bias = dir ? b_b : b_f;
    float bg0 = bias[u], bg1 = bias[128 + u], bg2 = bias[256 + u], bg3 = bias[384 + u];
    const float4* Wp = (const float4*)(g_Wip + dir * EMBD * GDIM) + u;
    __syncthreads();

    for (int t = 0; t < T_STEPS; t++) {
        __syncthreads();  // previous iteration's x2s readers done
#pragma unroll
        for (int i = 0; i < 4; i++) {
            int idx = u + i * 128;            // 0..511 over (r,e)
            int r = idx >> 6, e = idx & 63;
            const float* fb = lf + (r0 + r) * 600 + 200 + t * 4;
            float v = eB[e];
            v = fmaf(fb[0], eW[e],        v);
            v = fmaf(fb[1], eW[64  + e],  v);
            v = fmaf(fb[2], eW[128 + e],  v);
            v = fmaf(fb[3], eW[192 + e],  v);
            v = fmaxf(v, 0.0f);
            ((float*)&x2s[r >> 1][e])[r & 1] = v;
        }
        __syncthreads();

        unsigned long long a0[PAIRS], a1[PAIRS], a2[PAIRS], a3[PAIRS];
#pragma unroll
        for (int p = 0; p < PAIRS; p++) {
            a0[p] = pack2(bg0, bg0); a1[p] = pack2(bg1, bg1);
            a2[p] = pack2(bg2, bg2); a3[p] = pack2(bg3, bg3);
        }
#pragma unroll 2
        for (int k = 0; k < EMBD; k++) {
            float4 w4 = Wp[k * 128];
            unsigned long long w0 = pack2(w4.x, w4.x);
            unsigned long long w1 = pack2(w4.y, w4.y);
            unsigned long long w2 = pack2(w4.z, w4.z);
            unsigned long long w3 = pack2(w4.w, w4.w);
#pragma unroll
            for (int p = 0; p < PAIRS; p++) {
                unsigned long long xv = *(const unsigned long long*)&x2s[p][k];
                fma2(a0[p], xv, w0); fma2(a1[p], xv, w1);
                fma2(a2[p], xv, w2); fma2(a3[p], xv, w3);
            }
        }
        long tile = ((long)(dir * T_STEPS + t) * nblk + mblk) * 4096L;
#pragma unroll
        for (int p = 0; p < PAIRS; p++) {
            float4* op = (float4*)(g_xg + tile + (long)(p * 128 + u) * 8);
            float2 v0 = unpack2(a0[p]), v1 = unpack2(a1[p]);
            float2 v2 = unpack2(a2[p]), v3 = unpack2(a3[p]);
            op[0] = make_float4(v0.x, v0.y, v1.x, v1.y);
            op[1] = make_float4(v2.x, v2.y, v3.x, v3.y);
        }
    }
}

// ---------------------------------------------------------------------------
// Kernel 4: recurrent bidirectional LSTM (h @ Whh only; x-gates preloaded).
// Grid: 2 * (M/ROWS) CTAs of 128 threads. Thread u owns hidden unit u for
// all 8 rows (4 f32x2 pairs). Online front/back/max/attn reductions.
// ---------------------------------------------------------------------------
__global__ void __launch_bounds__(128, 5)
lstm_kernel(const float* __restrict__ h0, const float* __restrict__ c0,
            const int*   __restrict__ mask, int Mrows) {
    int nblk = Mrows / ROWS;
    int dir  = blockIdx.x / nblk;
    int mblk = blockIdx.x % nblk;
    int r0   = mblk * ROWS;
    int u    = threadIdx.x;

    __shared__ float2 h2s[PAIRS][HID];
    __shared__ float  attv[ROWS];
    __shared__ int    mrow[ROWS];

    if (u < ROWS) mrow[u] = mask[r0 + u];

    const float4* Wp = (const float4*)(g_Whp + dir * HID * GDIM) + u;
    float h0v = h0[dir * HID + u];
    float c0v = c0[dir * HID + u];

    float2 hreg[PAIRS], c2[PAIRS], hmax[PAIRS], hatt[PAIRS];
#pragma unroll
    for (int p = 0; p < PAIRS; p++) {
        hreg[p] = make_float2(h0v, h0v);
        c2[p]   = make_float2(c0v, c0v);
        hmax[p] = make_float2(-1e30f, -1e30f);
        hatt[p] = make_float2(0.0f, 0.0f);
    }

    for (int s = 0; s < T_STEPS; s++) {
        int t = dir ? (T_STEPS - 1 - s) : s;

        __syncthreads();  // all readers of previous h2s done
#pragma unroll
        for (int p = 0; p < PAIRS; p++) h2s[p][u] = hreg[p];
        if (u < ROWS) attv[u] = g_scores[mrow[u] * T_STEPS + t];

        // preload x-gate accumulators (bias already folded in)
        unsigned long long a0[PAIRS], a1[PAIRS], a2[PAIRS], a3[PAIRS];
        long tile = ((long)(dir * T_STEPS + t) * nblk + mblk) * 4096L;
#pragma unroll
        for (int p = 0; p < PAIRS; p++) {
            const float4* xp = (const float4*)(g_xg + tile + (long)(p * 128 + u) * 8);
            float4 A = xp[0], B = xp[1];
            a0[p] = pack2(A.x, A.y); a1[p] = pack2(A.z, A.w);
            a2[p] = pack2(B.x, B.y); a3[p] = pack2(B.z, B.w);
        }
        __syncthreads();  // h2s / attv published

#pragma unroll 2
        for (int k = 0; k < HID; k++) {
            float4 w4 = Wp[k * 128];
            unsigned long long w0 = pack2(w4.x, w4.x);
            unsigned long long w1 = pack2(w4.y, w4.y);
            unsigned long long w2 = pack2(w4.z, w4.z);
            unsigned long long w3 = pack2(w4.w, w4.w);
#pragma unroll
            for (int p = 0; p < PAIRS; p++) {
                unsigned long long hv = *(const unsigned long long*)&h2s[p][k];
                fma2(a0[p], hv, w0); fma2(a1[p], hv, w1);
                fma2(a2[p], hv, w2); fma2(a3[p], hv, w3);
            }
        }

#pragma unroll
        for (int p = 0; p < PAIRS; p++) {
            float2 gi = unpack2(a0[p]);
            float2 gf = unpack2(a1[p]);
            float2 gg = unpack2(a2[p]);
            float2 go = unpack2(a3[p]);
            float cx = sigf(gf.x) * c2[p].x + sigf(gi.x) * tanhfast(gg.x);
            float cy = sigf(gf.y) * c2[p].y + sigf(gi.y) * tanhfast(gg.y);
            c2[p].x = cx; c2[p].y = cy;
            float hx = sigf(go.x) * tanhfast(cx);
            float hy = sigf(go.y) * tanhfast(cy);
            hreg[p] = make_float2(hx, hy);
            hmax[p].x = fmaxf(hmax[p].x, hx);
            hmax[p].y = fmaxf(hmax[p].y, hy);
            float ax = attv[2 * p], ay = attv[2 * p + 1];
            hatt[p].x = fmaf(hx, ax, hatt[p].x);
            hatt[p].y = fmaf(hy, ay, hatt[p].y);
            if (t == 0) {
                g_pre[(r0 + 2 * p)     * 1024 + dir * HID + u] = hx;
                g_pre[(r0 + 2 * p + 1) * 1024 + dir * HID + u] = hy;
            }
            if (t == T_STEPS - 1) {
                g_pre[(r0 + 2 * p)     * 1024 + 256 + dir * HID + u] = hx;
                g_pre[(r0 + 2 * p + 1) * 1024 + 256 + dir * HID + u] = hy;
            }
        }
    }

#pragma unroll
    for (int p = 0; p < PAIRS; p++) {
        g_pre[(r0 + 2 * p)     * 1024 + 512 + dir * HID + u] = hmax[p].x;
        g_pre[(r0 + 2 * p + 1) * 1024 + 512 + dir * HID + u] = hmax[p].y;
        g_pre[(r0 + 2 * p)     * 1024 + 768 + dir * HID + u] = hatt[p].x;
        g_pre[(r0 + 2 * p + 1) * 1024 + 768 + dir * HID + u] = hatt[p].y;
    }
}

// ---------------------------------------------------------------------------
// Kernel 5: out = relu(pre(M,1024) @ enc_W(1024,128) + enc_b)
// 8 rows per block (4 pairs), 128 threads = one output column each.
// ---------------------------------------------------------------------------
__global__ void __launch_bounds__(128)
out_kernel(const float* __restrict__ encW, const float* __restrict__ encB,
           float* __restrict__ out) {
    int r0 = blockIdx.x * ROWS;
    int c  = threadIdx.x;
    __shared__ float2 ps[PAIRS][64];

    float bc = encB[c];
    unsigned long long acc[PAIRS];
#pragma unroll
    for (int p = 0; p < PAIRS; p++) acc[p] = pack2(bc, bc);

    for (int kt = 0; kt < 1024; kt += 64) {
        __syncthreads();
#pragma unroll
        for (int i = 0; i < 4; i++) {
            int idx = c + i * 128;           // 0..511 over (r, kk)
            int r = idx >> 6, kk = idx & 63;
            ((float*)&ps[r >> 1][kk])[r & 1] = g_pre[(r0 + r) * 1024 + kt + kk];
        }
        __syncthreads();
#pragma unroll 4
        for (int kk = 0; kk < 64; kk++) {
            float w = encW[(kt + kk) * 128 + c];
            unsigned long long w2 = pack2(w, w);
#pragma unroll
            for (int p = 0; p < PAIRS; p++) {
                unsigned long long pv = *(const unsigned long long*)&ps[p][kk];
                fma2(acc[p], pv, w2);
            }
        }
    }
#pragma unroll
    for (int p = 0; p < PAIRS; p++) {
        float2 v = unpack2(acc[p]);
        out[(r0 + 2 * p)     * 128 + c] = fmaxf(v.x, 0.0f);
        out[(r0 + 2 * p + 1) * 128 + c] = fmaxf(v.y, 0.0f);
    }
}

// ---------------------------------------------------------------------------
// Launch
// ---------------------------------------------------------------------------
extern "C" void kernel_launch(void* const* d_in, const int* in_sizes, int n_in,
                              void* d_out, int out_size) {
    const float* lf    = (const float*)d_in[0];
    const float* obs   = (const float*)d_in[1];
    const float* embW  = (const float*)d_in[2];
    const float* embB  = (const float*)d_in[3];
    const float* attW  = (const float*)d_in[4];
    const float* attB  = (const float*)d_in[5];
    const float* Wih_f = (const float*)d_in[6];
    const float* Whh_f = (const float*)d_in[7];
    const float* b_f   = (const float*)d_in[8];
    const float* Wih_b = (const float*)d_in[9];
    const float* Whh_b = (const float*)d_in[10];
    const float* b_b   = (const float*)d_in[11];
    const float* h0    = (const float*)d_in[12];
    const float* c0    = (const float*)d_in[13];
    const float* encW  = (const float*)d_in[14];
    const float* encB  = (const float*)d_in[15];
    const int*   mask  = (const int*)d_in[16];

    int M    = in_sizes[16];       // 4096
    int Nobs = in_sizes[1] / 128;  // 256

    pack_kernel<<<(2 * 192 * GDIM + 255) / 256, 256>>>(Wih_f, Whh_f, Wih_b, Whh_b);
    attn_kernel<<<Nobs, 128>>>(obs, attW, attB);
    xgate_kernel<<<2 * (M / ROWS), 128>>>(lf, embW, embB, b_f, b_b, M);
    lstm_kernel<<<2 * (M / ROWS), 128>>>(h0, c0, mask, M);
    out_kernel<<<M / ROWS, 128>>>(encW, encB, (float*)d_out);
}